// round 13
// baseline (speedup 1.0000x reference)
#include <cuda_runtime.h>
#include <cuda_fp16.h>
#include <math.h>
#include <stdint.h>

#define BATCH 8
#define SEQ   2048
#define EMB   1024
#define HD    64
#define NROWS (BATCH*SEQ)   // 16384

__device__ __half g_q[NROWS*HD];     // pre-scaled by log2(e)/64
__device__ __half g_k[NROWS*HD];
__device__ __half g_v[NROWS*HD];
__device__ __half g_wt[3][HD*EMB];   // [o][n][k] transposed fp16
// flash-decoding partials (fixed m=0)
__device__ float g_po[2][NROWS*HD];
__device__ float g_pl[2][NROWS];
__device__ unsigned g_cnt[32*8];     // per (qt,b) completion counter (zero-init; reset after use)

// ---------------------------------------------------------------------------
__device__ __forceinline__ void mma_f16(float d[4],
                                        uint32_t a0, uint32_t a1, uint32_t a2, uint32_t a3,
                                        uint32_t b0, uint32_t b1) {
    asm volatile(
        "mma.sync.aligned.m16n8k16.row.col.f32.f16.f16.f32 "
        "{%0,%1,%2,%3},{%4,%5,%6,%7},{%8,%9},{%0,%1,%2,%3};\n"
        : "+f"(d[0]), "+f"(d[1]), "+f"(d[2]), "+f"(d[3])
        : "r"(a0), "r"(a1), "r"(a2), "r"(a3), "r"(b0), "r"(b1));
}
__device__ __forceinline__ uint32_t pack_h2(float lo, float hi) {
    __half2 h = __floats2half2_rn(lo, hi);
    return *(uint32_t*)&h;
}
__device__ __forceinline__ void ldmatrix_x4_t(uint32_t r[4], uint32_t saddr) {
    asm volatile("ldmatrix.sync.aligned.m8n8.x4.trans.shared.b16 {%0,%1,%2,%3}, [%4];"
                 : "=r"(r[0]), "=r"(r[1]), "=r"(r[2]), "=r"(r[3]) : "r"(saddr));
}
__device__ __forceinline__ void ldmatrix_x4(uint32_t r[4], uint32_t saddr) {
    asm volatile("ldmatrix.sync.aligned.m8n8.x4.shared.b16 {%0,%1,%2,%3}, [%4];"
                 : "=r"(r[0]), "=r"(r[1]), "=r"(r[2]), "=r"(r[3]) : "r"(saddr));
}
__device__ __forceinline__ void cp16(uint32_t smem_dst, const void* gsrc) {
    asm volatile("cp.async.cg.shared.global [%0], [%1], 16;\n"
                 :: "r"(smem_dst), "l"(gsrc));
}
__device__ __forceinline__ float ex2f(float x) {
    float r;
    asm("ex2.approx.f32 %0, %1;" : "=f"(r) : "f"(x));
    return r;
}

#define SCQ (1.4426950408889634f / 64.f)   // log2(e)/64, folded into q

// ============================================================================
// W -> fp16, transposed to [n][k]
// ============================================================================
__global__ __launch_bounds__(256) void wtrans_kernel(
    const float* __restrict__ Wq, const float* __restrict__ Wk,
    const float* __restrict__ Wv)
{
    __shared__ float Ts[64][65];
    const float* src = (blockIdx.y == 0) ? Wq : (blockIdx.y == 1) ? Wk : Wv;
    const int k0 = blockIdx.x * 64;
    const int tid = threadIdx.x;
#pragma unroll
    for (int s = 0; s < 16; s++) {
        int e = tid + 256 * s;
        int kk = e >> 6, n = e & 63;
        Ts[kk][n] = src[(size_t)(k0 + kk) * HD + n];
    }
    __syncthreads();
#pragma unroll
    for (int s = 0; s < 16; s++) {
        int e = tid + 256 * s;
        int n = e >> 6, kk = e & 63;
        g_wt[blockIdx.y][(size_t)n * EMB + k0 + kk] = __float2half(Ts[kk][n]);
    }
}

// ============================================================================
// Fused projection: A via register-prefetch LDG+cvt+STS, B via raw cp.async,
// ONE barrier per k-iteration, 3 CTAs/SM target.
// ============================================================================
#define PSTR 36
#define PROJ_SMEM ((2*64*PSTR + 3*2*64*PSTR) * 4)

__global__ __launch_bounds__(256, 3) void proj_kernel(const float* __restrict__ x)
{
    extern __shared__ uint32_t psm[];
    uint32_t* As = psm;
    uint32_t* Bs = psm + 2 * 64 * PSTR;
    const uint32_t Bs_u = (uint32_t)__cvta_generic_to_shared(Bs);

    const int m0   = blockIdx.x * 64;
    const int tid  = threadIdx.x;
    const int w    = tid >> 5;
    const int lane = tid & 31;
    const int g    = lane >> 2;
    const int t    = lane & 3;
    const int wm   = w >> 2;
    const int wn   = w & 3;

    float acc[3][2][2][4];
#pragma unroll
    for (int o = 0; o < 3; o++)
#pragma unroll
        for (int i = 0; i < 2; i++)
#pragma unroll
            for (int j = 0; j < 2; j++)
#pragma unroll
                for (int q = 0; q < 4; q++) acc[o][i][j][q] = 0.f;

    float4 pa[2][2];

    auto ldgA = [&](int k0c) {
#pragma unroll
        for (int s = 0; s < 2; s++) {
            int idx = tid + 256 * s;
            int r = idx >> 3, c = idx & 7;
            const float* src = &x[(size_t)(m0 + r) * EMB + k0c + c * 8];
            pa[s][0] = *(const float4*)src;
            pa[s][1] = *(const float4*)(src + 4);
        }
    };
    auto stsA = [&](int buf) {
#pragma unroll
        for (int s = 0; s < 2; s++) {
            int idx = tid + 256 * s;
            int r = idx >> 3, c = idx & 7;
            uint4 v;
            v.x = pack_h2(pa[s][0].x, pa[s][0].y);
            v.y = pack_h2(pa[s][0].z, pa[s][0].w);
            v.z = pack_h2(pa[s][1].x, pa[s][1].y);
            v.w = pack_h2(pa[s][1].z, pa[s][1].w);
            *(uint4*)&As[buf * 64 * PSTR + r * PSTR + c * 4] = v;
        }
    };
    auto cpB = [&](int buf, int k0c) {
#pragma unroll
        for (int o = 0; o < 3; o++) {
#pragma unroll
            for (int s = 0; s < 2; s++) {
                int idx = tid + 256 * s;
                int n = idx >> 3, c = idx & 7;
                cp16(Bs_u + ((o * 2 + buf) * 64 * PSTR + n * PSTR + c * 4) * 4,
                     &g_wt[o][(size_t)n * EMB + k0c + c * 8]);
            }
        }
        asm volatile("cp.async.commit_group;\n");
    };

    ldgA(0);
    cpB(0, 0);

    for (int it = 0; it < 16; it++) {
        const int buf = it & 1;
        stsA(buf);                                   // A(it) from regs
        asm volatile("cp.async.wait_group 0;\n");    // B(it) landed
        __syncthreads();                             // tiles visible; compute(it-1) done everywhere
        if (it + 1 < 16) {                           // prefetch it+1 (overlaps compute)
            ldgA((it + 1) * 64);
            cpB(buf ^ 1, (it + 1) * 64);
        }

        const uint32_t* Ab = As + buf * 64 * PSTR;
#pragma unroll
        for (int ks = 0; ks < 4; ks++) {
            uint32_t a[2][4];
#pragma unroll
            for (int am = 0; am < 2; am++) {
                int rb = wm * 32 + am * 16;
                a[am][0] = Ab[(rb + g) * PSTR + ks * 8 + t];
                a[am][1] = Ab[(rb + g + 8) * PSTR + ks * 8 + t];
                a[am][2] = Ab[(rb + g) * PSTR + ks * 8 + t + 4];
                a[am][3] = Ab[(rb + g + 8) * PSTR + ks * 8 + t + 4];
            }
#pragma unroll
            for (int o = 0; o < 3; o++) {
                const uint32_t* Bb = Bs + (o * 2 + buf) * 64 * PSTR;
#pragma unroll
                for (int bn = 0; bn < 2; bn++) {
                    int nb = wn * 16 + bn * 8;
                    uint32_t b0 = Bb[(nb + g) * PSTR + ks * 8 + t];
                    uint32_t b1 = Bb[(nb + g) * PSTR + ks * 8 + t + 4];
#pragma unroll
                    for (int am = 0; am < 2; am++)
                        mma_f16(acc[o][am][bn], a[am][0], a[am][1], a[am][2], a[am][3], b0, b1);
                }
            }
        }
    }

    __half* outs[3] = {g_q, g_k, g_v};
#pragma unroll
    for (int o = 0; o < 3; o++) {
        const float sc = (o == 0) ? SCQ : 1.f;
#pragma unroll
        for (int am = 0; am < 2; am++)
#pragma unroll
            for (int bn = 0; bn < 2; bn++) {
                int r0 = m0 + wm * 32 + am * 16 + g;
                int c  = wn * 16 + bn * 8 + 2 * t;
                *(__half2*)&outs[o][(size_t)r0 * HD + c] =
                    __floats2half2_rn(acc[o][am][bn][0] * sc, acc[o][am][bn][1] * sc);
                *(__half2*)&outs[o][(size_t)(r0 + 8) * HD + c] =
                    __floats2half2_rn(acc[o][am][bn][2] * sc, acc[o][am][bn][3] * sc);
            }
    }
}

// ============================================================================
// Flash attention: fixed-m softmax + cp.async pipeline + fused merge
// (last-block-merges via threadfence + atomic counter).
// ============================================================================
#define QSTR 36
#define KVW  (64*QSTR)
#define ONES_H2 0x3C003C00u

__global__ __launch_bounds__(128, 4) void attn_kernel(float* __restrict__ out)
{
    __shared__ uint32_t Qs[64 * QSTR];
    __shared__ uint32_t Ks[2][KVW];
    __shared__ uint32_t Vs[2][KVW];
    __shared__ unsigned s_done;

    const int bx   = blockIdx.x;
    const int qt   = 31 - (bx >> 4);
    const int sub  = bx & 15;
    const int b    = sub >> 1;
    const int half = sub & 1;
    const int q0   = qt * 64;

    const int nk     = qt + 1;
    const int nhalf  = (nk + 1) >> 1;
    const int kt_beg = half ? nhalf : 0;
    const int kt_end = half ? nk : nhalf;
    const int niter  = kt_end - kt_beg;

    const __half* Qg = g_q + (size_t)b * SEQ * HD;
    const __half* Kg = g_k + (size_t)b * SEQ * HD;
    const __half* Vg = g_v + (size_t)b * SEQ * HD;

    const int tid  = threadIdx.x;
    const int lane = tid & 31;
    const int w    = tid >> 5;
    const int g    = lane >> 2;
    const int t    = lane & 3;
    const int qb   = w * 16;

    const uint32_t Ks_u = (uint32_t)__cvta_generic_to_shared(Ks);
    const uint32_t Vs_u = (uint32_t)__cvta_generic_to_shared(Vs);

    auto stageKV = [&](int buf, int kt) {
        const int k0 = kt * 64;
#pragma unroll
        for (int s = 0; s < 4; s++) {
            int idx = tid + 128 * s;
            int r = idx >> 3, c = idx & 7;
            cp16(Ks_u + (buf * KVW + r * QSTR + c * 4) * 4,
                 &Kg[(size_t)(k0 + r) * HD + c * 8]);
            cp16(Vs_u + (buf * KVW + r * QSTR + c * 4) * 4,
                 &Vg[(size_t)(k0 + r) * HD + c * 8]);
        }
        asm volatile("cp.async.commit_group;\n");
    };

    if (niter > 0) stageKV(0, kt_beg);

#pragma unroll
    for (int s = 0; s < 4; s++) {
        int idx = tid + 128 * s;
        int r = idx >> 3, c = idx & 7;
        *(uint4*)&Qs[r * QSTR + c * 4] = *(const uint4*)&Qg[(size_t)(q0 + r) * HD + c * 8];
    }
    __syncthreads();

    uint32_t aQ[4][4];
#pragma unroll
    for (int ks = 0; ks < 4; ks++) {
        aQ[ks][0] = Qs[(qb + g) * QSTR + ks * 8 + t];
        aQ[ks][1] = Qs[(qb + g + 8) * QSTR + ks * 8 + t];
        aQ[ks][2] = Qs[(qb + g) * QSTR + ks * 8 + t + 4];
        aQ[ks][3] = Qs[(qb + g + 8) * QSTR + ks * 8 + t + 4];
    }

    float o_[8][4];
    float lsum[4] = {0.f, 0.f, 0.f, 0.f};
#pragma unroll
    for (int bn = 0; bn < 8; bn++)
#pragma unroll
        for (int q = 0; q < 4; q++) o_[bn][q] = 0.f;

    const uint32_t vrow_off = ((lane & 15) * QSTR + (lane >> 4) * 4) * 4;
    const uint32_t krow_off =
        (((lane & 7) + ((lane >> 4) << 3)) * QSTR + ((lane >> 3) & 1) * 4) * 4;

    for (int i = 0; i < niter; i++) {
        const int buf = i & 1;
        const int kt  = kt_beg + i;
        const int k0  = kt * 64;

        asm volatile("cp.async.wait_group 0;\n");
        __syncthreads();
        if (i + 1 < niter) stageKV(buf ^ 1, kt + 1);

        const uint32_t KbU = Ks_u + buf * KVW * 4;

        float sa[8][4];
#pragma unroll
        for (int bn = 0; bn < 8; bn++)
#pragma unroll
            for (int q = 0; q < 4; q++) sa[bn][q] = 0.f;
#pragma unroll
        for (int ks = 0; ks < 4; ks++) {
#pragma unroll
            for (int bnq = 0; bnq < 4; bnq++) {
                uint32_t kb[4];
                ldmatrix_x4(kb, KbU + (bnq * 16 * QSTR + ks * 8) * 4 + krow_off);
                mma_f16(sa[2 * bnq],     aQ[ks][0], aQ[ks][1], aQ[ks][2], aQ[ks][3], kb[0], kb[1]);
                mma_f16(sa[2 * bnq + 1], aQ[ks][0], aQ[ks][1], aQ[ks][2], aQ[ks][3], kb[2], kb[3]);
            }
        }

        if (kt == qt) {
#pragma unroll
            for (int bn = 0; bn < 8; bn++)
#pragma unroll
                for (int q = 0; q < 4; q++) {
                    int col = k0 + bn * 8 + 2 * t + (q & 1);
                    int row = q0 + qb + g + ((q >= 2) ? 8 : 0);
                    if (col > row) sa[bn][q] = -30000.f;
                }
        }

        uint32_t pA[4][4];
#pragma unroll
        for (int bn = 0; bn < 8; bn++) {
            float p0 = ex2f(sa[bn][0]);
            float p1 = ex2f(sa[bn][1]);
            float p2 = ex2f(sa[bn][2]);
            float p3 = ex2f(sa[bn][3]);
            int ks = bn >> 1;
            if ((bn & 1) == 0) {
                pA[ks][0] = pack_h2(p0, p1);
                pA[ks][1] = pack_h2(p2, p3);
            } else {
                pA[ks][2] = pack_h2(p0, p1);
                pA[ks][3] = pack_h2(p2, p3);
            }
        }

#pragma unroll
        for (int ks = 0; ks < 4; ks++)
            mma_f16(lsum, pA[ks][0], pA[ks][1], pA[ks][2], pA[ks][3], ONES_H2, ONES_H2);

        const uint32_t Vb_u = Vs_u + buf * KVW * 4;
#pragma unroll
        for (int ks = 0; ks < 4; ks++) {
#pragma unroll
            for (int bnp = 0; bnp < 4; bnp++) {
                uint32_t vb[4];
                ldmatrix_x4_t(vb, Vb_u + (ks * 16 * QSTR + bnp * 8) * 4 + vrow_off);
                mma_f16(o_[2 * bnp],     pA[ks][0], pA[ks][1], pA[ks][2], pA[ks][3], vb[0], vb[1]);
                mma_f16(o_[2 * bnp + 1], pA[ks][0], pA[ks][1], pA[ks][2], pA[ks][3], vb[2], vb[3]);
            }
        }
    }

    // write unnormalized partials
    const int r0g = b * SEQ + q0 + qb + g;
    if (t == 0) {
        g_pl[half][r0g]     = lsum[0];
        g_pl[half][r0g + 8] = lsum[2];
    }
#pragma unroll
    for (int bn = 0; bn < 8; bn++) {
        int c = bn * 8 + 2 * t;
        *(float2*)&g_po[half][(size_t)r0g * HD + c] = make_float2(o_[bn][0], o_[bn][1]);
        *(float2*)&g_po[half][(size_t)(r0g + 8) * HD + c] = make_float2(o_[bn][2], o_[bn][3]);
    }

    // ---- fused merge: second-arriving block combines both halves ----
    __threadfence();
    if (tid == 0) s_done = atomicAdd(&g_cnt[(qt << 3) | b], 1);
    __syncthreads();
    if (s_done == 1) {
        if (tid == 0) g_cnt[(qt << 3) | b] = 0;   // reset for next graph replay
        const int rowbase = b * SEQ + q0;
        // 64 rows x 16 float4 = 1024 chunks / 128 thr = 8 per thread
#pragma unroll
        for (int s = 0; s < 8; s++) {
            int idx = tid + 128 * s;
            int r = idx >> 4;               // 0..63
            int c = (idx & 15) * 4;
            int row = rowbase + r;
            float inv = 1.f / (g_pl[0][row] + g_pl[1][row]);
            float4 a = *(const float4*)&g_po[0][(size_t)row * HD + c];
            float4 bb = *(const float4*)&g_po[1][(size_t)row * HD + c];
            float4 rr;
            rr.x = (a.x + bb.x) * inv;
            rr.y = (a.y + bb.y) * inv;
            rr.z = (a.z + bb.z) * inv;
            rr.w = (a.w + bb.w) * inv;
            *(float4*)&out[(size_t)row * HD + c] = rr;
        }
    }
}

// ============================================================================
extern "C" void kernel_launch(void* const* d_in, const int* in_sizes, int n_in,
                              void* d_out, int out_size)
{
    const float* x  = (const float*)d_in[0];
    const float* Wq = (const float*)d_in[1];
    const float* Wk = (const float*)d_in[2];
    const float* Wv = (const float*)d_in[3];
    float* out = (float*)d_out;

    wtrans_kernel<<<dim3(16, 3), 256>>>(Wq, Wk, Wv);

    cudaFuncSetAttribute(proj_kernel, cudaFuncAttributeMaxDynamicSharedMemorySize,
                         PROJ_SMEM);
    proj_kernel<<<NROWS / 64, 256, PROJ_SMEM>>>(x);

    attn_kernel<<<512, 128>>>(out);
}

// round 14
// speedup vs baseline: 1.2298x; 1.2298x over previous
#include <cuda_runtime.h>
#include <cuda_fp16.h>
#include <math.h>
#include <stdint.h>

#define BATCH 8
#define SEQ   2048
#define EMB   1024
#define HD    64
#define NROWS (BATCH*SEQ)   // 16384

__device__ __half g_q[NROWS*HD];     // pre-scaled by log2(e)/64
__device__ __half g_k[NROWS*HD];
__device__ __half g_v[NROWS*HD];
__device__ __half g_wt[3][HD*EMB];   // [o][n][k] transposed fp16
// flash-decoding partials (fixed m=0)
__device__ float g_po[2][NROWS*HD];
__device__ float g_pl[2][NROWS];
__device__ unsigned g_cnt[32*8];     // per (qt,b) counter (zero-init; reset after use)

// ---------------------------------------------------------------------------
__device__ __forceinline__ void mma_f16(float d[4],
                                        uint32_t a0, uint32_t a1, uint32_t a2, uint32_t a3,
                                        uint32_t b0, uint32_t b1) {
    asm volatile(
        "mma.sync.aligned.m16n8k16.row.col.f32.f16.f16.f32 "
        "{%0,%1,%2,%3},{%4,%5,%6,%7},{%8,%9},{%0,%1,%2,%3};\n"
        : "+f"(d[0]), "+f"(d[1]), "+f"(d[2]), "+f"(d[3])
        : "r"(a0), "r"(a1), "r"(a2), "r"(a3), "r"(b0), "r"(b1));
}
__device__ __forceinline__ uint32_t pack_h2(float lo, float hi) {
    __half2 h = __floats2half2_rn(lo, hi);
    return *(uint32_t*)&h;
}
__device__ __forceinline__ void ldmatrix_x4_t(uint32_t r[4], uint32_t saddr) {
    asm volatile("ldmatrix.sync.aligned.m8n8.x4.trans.shared.b16 {%0,%1,%2,%3}, [%4];"
                 : "=r"(r[0]), "=r"(r[1]), "=r"(r[2]), "=r"(r[3]) : "r"(saddr));
}
__device__ __forceinline__ void ldmatrix_x4(uint32_t r[4], uint32_t saddr) {
    asm volatile("ldmatrix.sync.aligned.m8n8.x4.shared.b16 {%0,%1,%2,%3}, [%4];"
                 : "=r"(r[0]), "=r"(r[1]), "=r"(r[2]), "=r"(r[3]) : "r"(saddr));
}
__device__ __forceinline__ void cp16(uint32_t smem_dst, const void* gsrc) {
    asm volatile("cp.async.cg.shared.global [%0], [%1], 16;\n"
                 :: "r"(smem_dst), "l"(gsrc));
}
__device__ __forceinline__ float ex2f(float x) {
    float r;
    asm("ex2.approx.f32 %0, %1;" : "=f"(r) : "f"(x));
    return r;
}

#define SCQ (1.4426950408889634f / 64.f)   // log2(e)/64, folded into q

// ============================================================================
// W -> fp16, transposed to [n][k].  grid (64,3): 16x64 tile per block.
// ============================================================================
__global__ __launch_bounds__(256) void wtrans_kernel(
    const float* __restrict__ Wq, const float* __restrict__ Wk,
    const float* __restrict__ Wv)
{
    __shared__ float Ts[16][65];
    const float* src = (blockIdx.y == 0) ? Wq : (blockIdx.y == 1) ? Wk : Wv;
    const int k0 = blockIdx.x * 16;
    const int tid = threadIdx.x;
#pragma unroll
    for (int s = 0; s < 4; s++) {
        int e = tid + 256 * s;          // 1024 elems: 16 k x 64 n
        int kk = e >> 6, n = e & 63;
        Ts[kk][n] = src[(size_t)(k0 + kk) * HD + n];
    }
    __syncthreads();
#pragma unroll
    for (int s = 0; s < 4; s++) {
        int e = tid + 256 * s;          // 64 n x 16 k
        int n = e >> 4, kk = e & 15;
        g_wt[blockIdx.y][(size_t)n * EMB + k0 + kk] = __float2half(Ts[kk][n]);
    }
}

// ============================================================================
// Fused projection (R12 version verbatim; q epilogue pre-scaled by SCQ)
// ============================================================================
#define PSTR 36
#define PROJ_SMEM ((2*64*PSTR + 3*2*64*PSTR) * 4)

__global__ __launch_bounds__(256, 2) void proj_kernel(const float* __restrict__ x)
{
    extern __shared__ uint32_t psm[];
    uint32_t* As = psm;
    uint32_t* Bs = psm + 2 * 64 * PSTR;

    const int m0   = blockIdx.x * 64;
    const int tid  = threadIdx.x;
    const int w    = tid >> 5;
    const int lane = tid & 31;
    const int g    = lane >> 2;
    const int t    = lane & 3;
    const int wm   = w >> 2;
    const int wn   = w & 3;

    float acc[3][2][2][4];
#pragma unroll
    for (int o = 0; o < 3; o++)
#pragma unroll
        for (int i = 0; i < 2; i++)
#pragma unroll
            for (int j = 0; j < 2; j++)
#pragma unroll
                for (int q = 0; q < 4; q++) acc[o][i][j][q] = 0.f;

    float4 pa[2][2];
    uint4  pb[3], pb2[3];

    auto ldg_iter = [&](int k0c) {
#pragma unroll
        for (int s = 0; s < 2; s++) {
            int idx = tid + 256 * s;
            int r = idx >> 3, c = idx & 7;
            const float* src = &x[(size_t)(m0 + r) * EMB + k0c + c * 8];
            pa[s][0] = *(const float4*)src;
            pa[s][1] = *(const float4*)(src + 4);
        }
#pragma unroll
        for (int o = 0; o < 3; o++) {
            int r = tid >> 3, c = tid & 7;
            pb[o] = *(const uint4*)&g_wt[o][(size_t)r * EMB + k0c + c * 8];
            int idx2 = tid + 256;
            int r2 = idx2 >> 3, c2 = idx2 & 7;
            pb2[o] = *(const uint4*)&g_wt[o][(size_t)r2 * EMB + k0c + c2 * 8];
        }
    };

    auto sts_iter = [&](int buf) {
#pragma unroll
        for (int s = 0; s < 2; s++) {
            int idx = tid + 256 * s;
            int r = idx >> 3, c = idx & 7;
            uint4 v;
            v.x = pack_h2(pa[s][0].x, pa[s][0].y);
            v.y = pack_h2(pa[s][0].z, pa[s][0].w);
            v.z = pack_h2(pa[s][1].x, pa[s][1].y);
            v.w = pack_h2(pa[s][1].z, pa[s][1].w);
            *(uint4*)&As[buf * 64 * PSTR + r * PSTR + c * 4] = v;
        }
#pragma unroll
        for (int o = 0; o < 3; o++) {
            {
                int r = tid >> 3, c = tid & 7;
                *(uint4*)&Bs[(o * 2 + buf) * 64 * PSTR + r * PSTR + c * 4] = pb[o];
            }
            {
                int idx = tid + 256;
                int r = idx >> 3, c = idx & 7;
                *(uint4*)&Bs[(o * 2 + buf) * 64 * PSTR + r * PSTR + c * 4] = pb2[o];
            }
        }
    };

    ldg_iter(0);

    for (int it = 0; it < 16; it++) {
        const int buf = it & 1;
        sts_iter(buf);
        __syncthreads();
        if (it + 1 < 16) ldg_iter((it + 1) * 64);

        const uint32_t* Ab = As + buf * 64 * PSTR;
#pragma unroll
        for (int ks = 0; ks < 4; ks++) {
            uint32_t a[2][4];
#pragma unroll
            for (int am = 0; am < 2; am++) {
                int rb = wm * 32 + am * 16;
                a[am][0] = Ab[(rb + g) * PSTR + ks * 8 + t];
                a[am][1] = Ab[(rb + g + 8) * PSTR + ks * 8 + t];
                a[am][2] = Ab[(rb + g) * PSTR + ks * 8 + t + 4];
                a[am][3] = Ab[(rb + g + 8) * PSTR + ks * 8 + t + 4];
            }
#pragma unroll
            for (int o = 0; o < 3; o++) {
                const uint32_t* Bb = Bs + (o * 2 + buf) * 64 * PSTR;
#pragma unroll
                for (int bn = 0; bn < 2; bn++) {
                    int nb = wn * 16 + bn * 8;
                    uint32_t b0 = Bb[(nb + g) * PSTR + ks * 8 + t];
                    uint32_t b1 = Bb[(nb + g) * PSTR + ks * 8 + t + 4];
#pragma unroll
                    for (int am = 0; am < 2; am++)
                        mma_f16(acc[o][am][bn], a[am][0], a[am][1], a[am][2], a[am][3], b0, b1);
                }
            }
        }
        __syncthreads();
    }

    __half* outs[3] = {g_q, g_k, g_v};
#pragma unroll
    for (int o = 0; o < 3; o++) {
        const float sc = (o == 0) ? SCQ : 1.f;
#pragma unroll
        for (int am = 0; am < 2; am++)
#pragma unroll
            for (int bn = 0; bn < 2; bn++) {
                int r0 = m0 + wm * 32 + am * 16 + g;
                int c  = wn * 16 + bn * 8 + 2 * t;
                *(__half2*)&outs[o][(size_t)r0 * HD + c] =
                    __floats2half2_rn(acc[o][am][bn][0] * sc, acc[o][am][bn][1] * sc);
                *(__half2*)&outs[o][(size_t)(r0 + 8) * HD + c] =
                    __floats2half2_rn(acc[o][am][bn][2] * sc, acc[o][am][bn][3] * sc);
            }
    }
}

// ============================================================================
// Flash attention (R12 core) + fused merge (second-arriving block merges).
// ============================================================================
#define QSTR 36
#define KVW  (64*QSTR)
#define ONES_H2 0x3C003C00u

__global__ __launch_bounds__(128, 4) void attn_kernel(float* __restrict__ out)
{
    __shared__ uint32_t Qs[64 * QSTR];
    __shared__ uint32_t Ks[2][KVW];
    __shared__ uint32_t Vs[2][KVW];
    __shared__ unsigned s_done;

    const int bx   = blockIdx.x;
    const int qt   = 31 - (bx >> 4);
    const int sub  = bx & 15;
    const int b    = sub >> 1;
    const int half = sub & 1;
    const int q0   = qt * 64;

    const int nk     = qt + 1;
    const int nhalf  = (nk + 1) >> 1;
    const int kt_beg = half ? nhalf : 0;
    const int kt_end = half ? nk : nhalf;
    const int niter  = kt_end - kt_beg;

    const __half* Qg = g_q + (size_t)b * SEQ * HD;
    const __half* Kg = g_k + (size_t)b * SEQ * HD;
    const __half* Vg = g_v + (size_t)b * SEQ * HD;

    const int tid  = threadIdx.x;
    const int lane = tid & 31;
    const int w    = tid >> 5;
    const int g    = lane >> 2;
    const int t    = lane & 3;
    const int qb   = w * 16;

    const uint32_t Ks_u = (uint32_t)__cvta_generic_to_shared(Ks);
    const uint32_t Vs_u = (uint32_t)__cvta_generic_to_shared(Vs);

    auto stageKV = [&](int buf, int kt) {
        const int k0 = kt * 64;
#pragma unroll
        for (int s = 0; s < 4; s++) {
            int idx = tid + 128 * s;
            int r = idx >> 3, c = idx & 7;
            cp16(Ks_u + (buf * KVW + r * QSTR + c * 4) * 4,
                 &Kg[(size_t)(k0 + r) * HD + c * 8]);
            cp16(Vs_u + (buf * KVW + r * QSTR + c * 4) * 4,
                 &Vg[(size_t)(k0 + r) * HD + c * 8]);
        }
        asm volatile("cp.async.commit_group;\n");
    };

    if (niter > 0) stageKV(0, kt_beg);

#pragma unroll
    for (int s = 0; s < 4; s++) {
        int idx = tid + 128 * s;
        int r = idx >> 3, c = idx & 7;
        *(uint4*)&Qs[r * QSTR + c * 4] = *(const uint4*)&Qg[(size_t)(q0 + r) * HD + c * 8];
    }
    __syncthreads();

    uint32_t aQ[4][4];
#pragma unroll
    for (int ks = 0; ks < 4; ks++) {
        aQ[ks][0] = Qs[(qb + g) * QSTR + ks * 8 + t];
        aQ[ks][1] = Qs[(qb + g + 8) * QSTR + ks * 8 + t];
        aQ[ks][2] = Qs[(qb + g) * QSTR + ks * 8 + t + 4];
        aQ[ks][3] = Qs[(qb + g + 8) * QSTR + ks * 8 + t + 4];
    }

    float o_[8][4];
    float lsum[4] = {0.f, 0.f, 0.f, 0.f};
#pragma unroll
    for (int bn = 0; bn < 8; bn++)
#pragma unroll
        for (int q = 0; q < 4; q++) o_[bn][q] = 0.f;

    const uint32_t vrow_off = ((lane & 15) * QSTR + (lane >> 4) * 4) * 4;
    const uint32_t krow_off =
        (((lane & 7) + ((lane >> 4) << 3)) * QSTR + ((lane >> 3) & 1) * 4) * 4;

    for (int i = 0; i < niter; i++) {
        const int buf = i & 1;
        const int kt  = kt_beg + i;
        const int k0  = kt * 64;

        asm volatile("cp.async.wait_group 0;\n");
        __syncthreads();
        if (i + 1 < niter) stageKV(buf ^ 1, kt + 1);

        const uint32_t KbU = Ks_u + buf * KVW * 4;

        float sa[8][4];
#pragma unroll
        for (int bn = 0; bn < 8; bn++)
#pragma unroll
            for (int q = 0; q < 4; q++) sa[bn][q] = 0.f;
#pragma unroll
        for (int ks = 0; ks < 4; ks++) {
#pragma unroll
            for (int bnq = 0; bnq < 4; bnq++) {
                uint32_t kb[4];
                ldmatrix_x4(kb, KbU + (bnq * 16 * QSTR + ks * 8) * 4 + krow_off);
                mma_f16(sa[2 * bnq],     aQ[ks][0], aQ[ks][1], aQ[ks][2], aQ[ks][3], kb[0], kb[1]);
                mma_f16(sa[2 * bnq + 1], aQ[ks][0], aQ[ks][1], aQ[ks][2], aQ[ks][3], kb[2], kb[3]);
            }
        }

        if (kt == qt) {
#pragma unroll
            for (int bn = 0; bn < 8; bn++)
#pragma unroll
                for (int q = 0; q < 4; q++) {
                    int col = k0 + bn * 8 + 2 * t + (q & 1);
                    int row = q0 + qb + g + ((q >= 2) ? 8 : 0);
                    if (col > row) sa[bn][q] = -30000.f;
                }
        }

        uint32_t pA[4][4];
#pragma unroll
        for (int bn = 0; bn < 8; bn++) {
            float p0 = ex2f(sa[bn][0]);
            float p1 = ex2f(sa[bn][1]);
            float p2 = ex2f(sa[bn][2]);
            float p3 = ex2f(sa[bn][3]);
            int ks = bn >> 1;
            if ((bn & 1) == 0) {
                pA[ks][0] = pack_h2(p0, p1);
                pA[ks][1] = pack_h2(p2, p3);
            } else {
                pA[ks][2] = pack_h2(p0, p1);
                pA[ks][3] = pack_h2(p2, p3);
            }
        }

#pragma unroll
        for (int ks = 0; ks < 4; ks++)
            mma_f16(lsum, pA[ks][0], pA[ks][1], pA[ks][2], pA[ks][3], ONES_H2, ONES_H2);

        const uint32_t Vb_u = Vs_u + buf * KVW * 4;
#pragma unroll
        for (int ks = 0; ks < 4; ks++) {
#pragma unroll
            for (int bnp = 0; bnp < 4; bnp++) {
                uint32_t vb[4];
                ldmatrix_x4_t(vb, Vb_u + (ks * 16 * QSTR + bnp * 8) * 4 + vrow_off);
                mma_f16(o_[2 * bnp],     pA[ks][0], pA[ks][1], pA[ks][2], pA[ks][3], vb[0], vb[1]);
                mma_f16(o_[2 * bnp + 1], pA[ks][0], pA[ks][1], pA[ks][2], pA[ks][3], vb[2], vb[3]);
            }
        }
    }

    const int r0g = b * SEQ + q0 + qb + g;
    if (t == 0) {
        g_pl[half][r0g]     = lsum[0];
        g_pl[half][r0g + 8] = lsum[2];
    }
#pragma unroll
    for (int bn = 0; bn < 8; bn++) {
        int c = bn * 8 + 2 * t;
        *(float2*)&g_po[half][(size_t)r0g * HD + c] = make_float2(o_[bn][0], o_[bn][1]);
        *(float2*)&g_po[half][(size_t)(r0g + 8) * HD + c] = make_float2(o_[bn][2], o_[bn][3]);
    }

    // ---- fused merge: second-arriving block combines both halves ----
    __threadfence();
    if (tid == 0) s_done = atomicAdd(&g_cnt[(qt << 3) | b], 1);
    __syncthreads();
    if (s_done == 1) {
        if (tid == 0) g_cnt[(qt << 3) | b] = 0;   // reset for next graph replay
        const int rowbase = b * SEQ + q0;
#pragma unroll
        for (int s = 0; s < 8; s++) {
            int idx = tid + 128 * s;
            int r = idx >> 4;
            int c = (idx & 15) * 4;
            int row = rowbase + r;
            float inv = 1.f / (g_pl[0][row] + g_pl[1][row]);
            float4 a = *(const float4*)&g_po[0][(size_t)row * HD + c];
            float4 bb = *(const float4*)&g_po[1][(size_t)row * HD + c];
            float4 rr;
            rr.x = (a.x + bb.x) * inv;
            rr.y = (a.y + bb.y) * inv;
            rr.z = (a.z + bb.z) * inv;
            rr.w = (a.w + bb.w) * inv;
            *(float4*)&out[(size_t)row * HD + c] = rr;
        }
    }
}

// ============================================================================
extern "C" void kernel_launch(void* const* d_in, const int* in_sizes, int n_in,
                              void* d_out, int out_size)
{
    const float* x  = (const float*)d_in[0];
    const float* Wq = (const float*)d_in[1];
    const float* Wk = (const float*)d_in[2];
    const float* Wv = (const float*)d_in[3];
    float* out = (float*)d_out;

    wtrans_kernel<<<dim3(64, 3), 256>>>(Wq, Wk, Wv);

    cudaFuncSetAttribute(proj_kernel, cudaFuncAttributeMaxDynamicSharedMemorySize,
                         PROJ_SMEM);
    proj_kernel<<<NROWS / 64, 256, PROJ_SMEM>>>(x);

    attn_kernel<<<512, 128>>>(out);
}

// round 15
// speedup vs baseline: 1.3120x; 1.0668x over previous
#include <cuda_runtime.h>
#include <cuda_fp16.h>
#include <math.h>
#include <stdint.h>

#define BATCH 8
#define SEQ   2048
#define EMB   1024
#define HD    64
#define NROWS (BATCH*SEQ)   // 16384

__device__ __half g_q[NROWS*HD];     // pre-scaled by log2(e)/64
__device__ __half g_k[NROWS*HD];
__device__ __half g_v[NROWS*HD];
__device__ __half g_wt[3][HD*EMB];   // [o][n][k] transposed fp16
// flash-decoding partials (fixed m=0), up to 4 kv-chunks per q-tile
__device__ float g_po[4][NROWS*HD];
__device__ float g_pl[4][NROWS];

// ---------------------------------------------------------------------------
__device__ __forceinline__ void mma_f16(float d[4],
                                        uint32_t a0, uint32_t a1, uint32_t a2, uint32_t a3,
                                        uint32_t b0, uint32_t b1) {
    asm volatile(
        "mma.sync.aligned.m16n8k16.row.col.f32.f16.f16.f32 "
        "{%0,%1,%2,%3},{%4,%5,%6,%7},{%8,%9},{%0,%1,%2,%3};\n"
        : "+f"(d[0]), "+f"(d[1]), "+f"(d[2]), "+f"(d[3])
        : "r"(a0), "r"(a1), "r"(a2), "r"(a3), "r"(b0), "r"(b1));
}
__device__ __forceinline__ uint32_t pack_h2(float lo, float hi) {
    __half2 h = __floats2half2_rn(lo, hi);
    return *(uint32_t*)&h;
}
__device__ __forceinline__ void ldmatrix_x4_t(uint32_t r[4], uint32_t saddr) {
    asm volatile("ldmatrix.sync.aligned.m8n8.x4.trans.shared.b16 {%0,%1,%2,%3}, [%4];"
                 : "=r"(r[0]), "=r"(r[1]), "=r"(r[2]), "=r"(r[3]) : "r"(saddr));
}
__device__ __forceinline__ void ldmatrix_x4(uint32_t r[4], uint32_t saddr) {
    asm volatile("ldmatrix.sync.aligned.m8n8.x4.shared.b16 {%0,%1,%2,%3}, [%4];"
                 : "=r"(r[0]), "=r"(r[1]), "=r"(r[2]), "=r"(r[3]) : "r"(saddr));
}
__device__ __forceinline__ void cp16(uint32_t smem_dst, const void* gsrc) {
    asm volatile("cp.async.cg.shared.global [%0], [%1], 16;\n"
                 :: "r"(smem_dst), "l"(gsrc));
}
__device__ __forceinline__ float ex2f(float x) {
    float r;
    asm("ex2.approx.f32 %0, %1;" : "=f"(r) : "f"(x));
    return r;
}

#define SCQ (1.4426950408889634f / 64.f)

// ============================================================================
// W -> fp16, transposed to [n][k].  grid (64,3): 16x64 tile per block.
// ============================================================================
__global__ __launch_bounds__(256) void wtrans_kernel(
    const float* __restrict__ Wq, const float* __restrict__ Wk,
    const float* __restrict__ Wv)
{
    __shared__ float Ts[16][65];
    const float* src = (blockIdx.y == 0) ? Wq : (blockIdx.y == 1) ? Wk : Wv;
    const int k0 = blockIdx.x * 16;
    const int tid = threadIdx.x;
#pragma unroll
    for (int s = 0; s < 4; s++) {
        int e = tid + 256 * s;
        int kk = e >> 6, n = e & 63;
        Ts[kk][n] = src[(size_t)(k0 + kk) * HD + n];
    }
    __syncthreads();
#pragma unroll
    for (int s = 0; s < 4; s++) {
        int e = tid + 256 * s;
        int n = e >> 4, kk = e & 15;
        g_wt[blockIdx.y][(size_t)n * EMB + k0 + kk] = __float2half(Ts[kk][n]);
    }
}

// ============================================================================
// Fused projection (R12 version verbatim)
// ============================================================================
#define PSTR 36
#define PROJ_SMEM ((2*64*PSTR + 3*2*64*PSTR) * 4)

__global__ __launch_bounds__(256, 2) void proj_kernel(const float* __restrict__ x)
{
    extern __shared__ uint32_t psm[];
    uint32_t* As = psm;
    uint32_t* Bs = psm + 2 * 64 * PSTR;

    const int m0   = blockIdx.x * 64;
    const int tid  = threadIdx.x;
    const int w    = tid >> 5;
    const int lane = tid & 31;
    const int g    = lane >> 2;
    const int t    = lane & 3;
    const int wm   = w >> 2;
    const int wn   = w & 3;

    float acc[3][2][2][4];
#pragma unroll
    for (int o = 0; o < 3; o++)
#pragma unroll
        for (int i = 0; i < 2; i++)
#pragma unroll
            for (int j = 0; j < 2; j++)
#pragma unroll
                for (int q = 0; q < 4; q++) acc[o][i][j][q] = 0.f;

    float4 pa[2][2];
    uint4  pb[3], pb2[3];

    auto ldg_iter = [&](int k0c) {
#pragma unroll
        for (int s = 0; s < 2; s++) {
            int idx = tid + 256 * s;
            int r = idx >> 3, c = idx & 7;
            const float* src = &x[(size_t)(m0 + r) * EMB + k0c + c * 8];
            pa[s][0] = *(const float4*)src;
            pa[s][1] = *(const float4*)(src + 4);
        }
#pragma unroll
        for (int o = 0; o < 3; o++) {
            int r = tid >> 3, c = tid & 7;
            pb[o] = *(const uint4*)&g_wt[o][(size_t)r * EMB + k0c + c * 8];
            int idx2 = tid + 256;
            int r2 = idx2 >> 3, c2 = idx2 & 7;
            pb2[o] = *(const uint4*)&g_wt[o][(size_t)r2 * EMB + k0c + c2 * 8];
        }
    };

    auto sts_iter = [&](int buf) {
#pragma unroll
        for (int s = 0; s < 2; s++) {
            int idx = tid + 256 * s;
            int r = idx >> 3, c = idx & 7;
            uint4 v;
            v.x = pack_h2(pa[s][0].x, pa[s][0].y);
            v.y = pack_h2(pa[s][0].z, pa[s][0].w);
            v.z = pack_h2(pa[s][1].x, pa[s][1].y);
            v.w = pack_h2(pa[s][1].z, pa[s][1].w);
            *(uint4*)&As[buf * 64 * PSTR + r * PSTR + c * 4] = v;
        }
#pragma unroll
        for (int o = 0; o < 3; o++) {
            {
                int r = tid >> 3, c = tid & 7;
                *(uint4*)&Bs[(o * 2 + buf) * 64 * PSTR + r * PSTR + c * 4] = pb[o];
            }
            {
                int idx = tid + 256;
                int r = idx >> 3, c = idx & 7;
                *(uint4*)&Bs[(o * 2 + buf) * 64 * PSTR + r * PSTR + c * 4] = pb2[o];
            }
        }
    };

    ldg_iter(0);

    for (int it = 0; it < 16; it++) {
        const int buf = it & 1;
        sts_iter(buf);
        __syncthreads();
        if (it + 1 < 16) ldg_iter((it + 1) * 64);

        const uint32_t* Ab = As + buf * 64 * PSTR;
#pragma unroll
        for (int ks = 0; ks < 4; ks++) {
            uint32_t a[2][4];
#pragma unroll
            for (int am = 0; am < 2; am++) {
                int rb = wm * 32 + am * 16;
                a[am][0] = Ab[(rb + g) * PSTR + ks * 8 + t];
                a[am][1] = Ab[(rb + g + 8) * PSTR + ks * 8 + t];
                a[am][2] = Ab[(rb + g) * PSTR + ks * 8 + t + 4];
                a[am][3] = Ab[(rb + g + 8) * PSTR + ks * 8 + t + 4];
            }
#pragma unroll
            for (int o = 0; o < 3; o++) {
                const uint32_t* Bb = Bs + (o * 2 + buf) * 64 * PSTR;
#pragma unroll
                for (int bn = 0; bn < 2; bn++) {
                    int nb = wn * 16 + bn * 8;
                    uint32_t b0 = Bb[(nb + g) * PSTR + ks * 8 + t];
                    uint32_t b1 = Bb[(nb + g) * PSTR + ks * 8 + t + 4];
#pragma unroll
                    for (int am = 0; am < 2; am++)
                        mma_f16(acc[o][am][bn], a[am][0], a[am][1], a[am][2], a[am][3], b0, b1);
                }
            }
        }
        __syncthreads();
    }

    __half* outs[3] = {g_q, g_k, g_v};
#pragma unroll
    for (int o = 0; o < 3; o++) {
        const float sc = (o == 0) ? SCQ : 1.f;
#pragma unroll
        for (int am = 0; am < 2; am++)
#pragma unroll
            for (int bn = 0; bn < 2; bn++) {
                int r0 = m0 + wm * 32 + am * 16 + g;
                int c  = wn * 16 + bn * 8 + 2 * t;
                *(__half2*)&outs[o][(size_t)r0 * HD + c] =
                    __floats2half2_rn(acc[o][am][bn][0] * sc, acc[o][am][bn][1] * sc);
                *(__half2*)&outs[o][(size_t)(r0 + 8) * HD + c] =
                    __floats2half2_rn(acc[o][am][bn][2] * sc, acc[o][am][bn][3] * sc);
            }
    }
}

// ============================================================================
// Flash attention (R12 core) with BALANCED work partition:
// nsplit(qt) = ceil((qt+1)/9) in {1..4}; grid = 8 * 74 = 592 = one full wave.
// ============================================================================
#define QSTR 36
#define KVW  (64*QSTR)
#define ONES_H2 0x3C003C00u

__global__ __launch_bounds__(128, 4) void attn_kernel()
{
    __shared__ uint32_t Qs[64 * QSTR];
    __shared__ uint32_t Ks[2][KVW];
    __shared__ uint32_t Vs[2][KVW];

    const int bx = blockIdx.x;
    const int b  = bx & 7;
    const int pair = bx >> 3;          // 0..73
    int qt, j;
    if (pair < 9)       { qt = pair;                 j = 0; }
    else if (pair < 27) { qt = 9  + (pair - 9) / 2;  j = (pair - 9) % 2; }
    else if (pair < 54) { qt = 18 + (pair - 27) / 3; j = (pair - 27) % 3; }
    else                { qt = 27 + (pair - 54) / 4; j = (pair - 54) % 4; }
    const int ns = (qt + 9) / 9;
    const int q0 = qt * 64;

    const int nk     = qt + 1;
    const int kt_beg = j * nk / ns;
    const int kt_end = (j + 1) * nk / ns;
    const int niter  = kt_end - kt_beg;

    const __half* Qg = g_q + (size_t)b * SEQ * HD;
    const __half* Kg = g_k + (size_t)b * SEQ * HD;
    const __half* Vg = g_v + (size_t)b * SEQ * HD;

    const int tid  = threadIdx.x;
    const int lane = tid & 31;
    const int w    = tid >> 5;
    const int g    = lane >> 2;
    const int t    = lane & 3;
    const int qb   = w * 16;

    const uint32_t Ks_u = (uint32_t)__cvta_generic_to_shared(Ks);
    const uint32_t Vs_u = (uint32_t)__cvta_generic_to_shared(Vs);

    auto stageKV = [&](int buf, int kt) {
        const int k0 = kt * 64;
#pragma unroll
        for (int s = 0; s < 4; s++) {
            int idx = tid + 128 * s;
            int r = idx >> 3, c = idx & 7;
            cp16(Ks_u + (buf * KVW + r * QSTR + c * 4) * 4,
                 &Kg[(size_t)(k0 + r) * HD + c * 8]);
            cp16(Vs_u + (buf * KVW + r * QSTR + c * 4) * 4,
                 &Vg[(size_t)(k0 + r) * HD + c * 8]);
        }
        asm volatile("cp.async.commit_group;\n");
    };

    if (niter > 0) stageKV(0, kt_beg);

#pragma unroll
    for (int s = 0; s < 4; s++) {
        int idx = tid + 128 * s;
        int r = idx >> 3, c = idx & 7;
        *(uint4*)&Qs[r * QSTR + c * 4] = *(const uint4*)&Qg[(size_t)(q0 + r) * HD + c * 8];
    }
    __syncthreads();

    uint32_t aQ[4][4];
#pragma unroll
    for (int ks = 0; ks < 4; ks++) {
        aQ[ks][0] = Qs[(qb + g) * QSTR + ks * 8 + t];
        aQ[ks][1] = Qs[(qb + g + 8) * QSTR + ks * 8 + t];
        aQ[ks][2] = Qs[(qb + g) * QSTR + ks * 8 + t + 4];
        aQ[ks][3] = Qs[(qb + g + 8) * QSTR + ks * 8 + t + 4];
    }

    float o_[8][4];
    float lsum[4] = {0.f, 0.f, 0.f, 0.f};
#pragma unroll
    for (int bn = 0; bn < 8; bn++)
#pragma unroll
        for (int q = 0; q < 4; q++) o_[bn][q] = 0.f;

    const uint32_t vrow_off = ((lane & 15) * QSTR + (lane >> 4) * 4) * 4;
    const uint32_t krow_off =
        (((lane & 7) + ((lane >> 4) << 3)) * QSTR + ((lane >> 3) & 1) * 4) * 4;

    for (int i = 0; i < niter; i++) {
        const int buf = i & 1;
        const int kt  = kt_beg + i;
        const int k0  = kt * 64;

        asm volatile("cp.async.wait_group 0;\n");
        __syncthreads();
        if (i + 1 < niter) stageKV(buf ^ 1, kt + 1);

        const uint32_t KbU = Ks_u + buf * KVW * 4;

        float sa[8][4];
#pragma unroll
        for (int bn = 0; bn < 8; bn++)
#pragma unroll
            for (int q = 0; q < 4; q++) sa[bn][q] = 0.f;
#pragma unroll
        for (int ks = 0; ks < 4; ks++) {
#pragma unroll
            for (int bnq = 0; bnq < 4; bnq++) {
                uint32_t kb[4];
                ldmatrix_x4(kb, KbU + (bnq * 16 * QSTR + ks * 8) * 4 + krow_off);
                mma_f16(sa[2 * bnq],     aQ[ks][0], aQ[ks][1], aQ[ks][2], aQ[ks][3], kb[0], kb[1]);
                mma_f16(sa[2 * bnq + 1], aQ[ks][0], aQ[ks][1], aQ[ks][2], aQ[ks][3], kb[2], kb[3]);
            }
        }

        if (kt == qt) {
#pragma unroll
            for (int bn = 0; bn < 8; bn++)
#pragma unroll
                for (int q = 0; q < 4; q++) {
                    int col = k0 + bn * 8 + 2 * t + (q & 1);
                    int row = q0 + qb + g + ((q >= 2) ? 8 : 0);
                    if (col > row) sa[bn][q] = -30000.f;
                }
        }

        uint32_t pA[4][4];
#pragma unroll
        for (int bn = 0; bn < 8; bn++) {
            float p0 = ex2f(sa[bn][0]);
            float p1 = ex2f(sa[bn][1]);
            float p2 = ex2f(sa[bn][2]);
            float p3 = ex2f(sa[bn][3]);
            int ks = bn >> 1;
            if ((bn & 1) == 0) {
                pA[ks][0] = pack_h2(p0, p1);
                pA[ks][1] = pack_h2(p2, p3);
            } else {
                pA[ks][2] = pack_h2(p0, p1);
                pA[ks][3] = pack_h2(p2, p3);
            }
        }

#pragma unroll
        for (int ks = 0; ks < 4; ks++)
            mma_f16(lsum, pA[ks][0], pA[ks][1], pA[ks][2], pA[ks][3], ONES_H2, ONES_H2);

        const uint32_t Vb_u = Vs_u + buf * KVW * 4;
#pragma unroll
        for (int ks = 0; ks < 4; ks++) {
#pragma unroll
            for (int bnp = 0; bnp < 4; bnp++) {
                uint32_t vb[4];
                ldmatrix_x4_t(vb, Vb_u + (ks * 16 * QSTR + bnp * 8) * 4 + vrow_off);
                mma_f16(o_[2 * bnp],     pA[ks][0], pA[ks][1], pA[ks][2], pA[ks][3], vb[0], vb[1]);
                mma_f16(o_[2 * bnp + 1], pA[ks][0], pA[ks][1], pA[ks][2], pA[ks][3], vb[2], vb[3]);
            }
        }
    }

    const int r0g = b * SEQ + q0 + qb + g;
    if (t == 0) {
        g_pl[j][r0g]     = lsum[0];
        g_pl[j][r0g + 8] = lsum[2];
    }
#pragma unroll
    for (int bn = 0; bn < 8; bn++) {
        int c = bn * 8 + 2 * t;
        *(float2*)&g_po[j][(size_t)r0g * HD + c] = make_float2(o_[bn][0], o_[bn][1]);
        *(float2*)&g_po[j][(size_t)(r0g + 8) * HD + c] = make_float2(o_[bn][2], o_[bn][3]);
    }
}

// ============================================================================
// Merge: sum the row's nsplit(qt) partials; fixed m -> plain sums.
// ============================================================================
__global__ __launch_bounds__(256) void merge_kernel(float* __restrict__ out)
{
    int gid = blockIdx.x * 256 + threadIdx.x;
    int row = gid >> 4;
    int c   = (gid & 15) * 4;
    const int qt = (row & (SEQ - 1)) >> 6;
    const int ns = (qt + 9) / 9;

    float lacc = g_pl[0][row];
    float4 a = *(const float4*)&g_po[0][(size_t)row * HD + c];
    for (int s = 1; s < ns; s++) {
        lacc += g_pl[s][row];
        float4 bb = *(const float4*)&g_po[s][(size_t)row * HD + c];
        a.x += bb.x; a.y += bb.y; a.z += bb.z; a.w += bb.w;
    }
    float inv = 1.f / lacc;
    a.x *= inv; a.y *= inv; a.z *= inv; a.w *= inv;
    *(float4*)&out[(size_t)row * HD + c] = a;
}

// ============================================================================
extern "C" void kernel_launch(void* const* d_in, const int* in_sizes, int n_in,
                              void* d_out, int out_size)
{
    const float* x  = (const float*)d_in[0];
    const float* Wq = (const float*)d_in[1];
    const float* Wk = (const float*)d_in[2];
    const float* Wv = (const float*)d_in[3];
    float* out = (float*)d_out;

    wtrans_kernel<<<dim3(64, 3), 256>>>(Wq, Wk, Wv);

    cudaFuncSetAttribute(proj_kernel, cudaFuncAttributeMaxDynamicSharedMemorySize,
                         PROJ_SMEM);
    proj_kernel<<<NROWS / 64, 256, PROJ_SMEM>>>(x);

    attn_kernel<<<592, 128>>>();

    merge_kernel<<<NROWS * 16 / 256, 256>>>(out);
}

// round 16
// speedup vs baseline: 1.3644x; 1.0400x over previous
#include <cuda_runtime.h>
#include <cuda_fp16.h>
#include <math.h>
#include <stdint.h>

#define BATCH 8
#define SEQ   2048
#define EMB   1024
#define HD    64
#define NROWS (BATCH*SEQ)   // 16384

__device__ __half g_q[NROWS*HD];     // pre-scaled by log2(e)/64
__device__ __half g_k[NROWS*HD];
__device__ __half g_v[NROWS*HD];
__device__ __half g_wt[3][HD*EMB];   // [o][n][k] transposed fp16
// flash-decoding partials (fixed m=0), up to 4 kv-chunks per q-tile
__device__ float g_po[4][NROWS*HD];
__device__ float g_pl[4][NROWS];

// ---------------------------------------------------------------------------
__device__ __forceinline__ void mma_f16(float d[4],
                                        uint32_t a0, uint32_t a1, uint32_t a2, uint32_t a3,
                                        uint32_t b0, uint32_t b1) {
    asm volatile(
        "mma.sync.aligned.m16n8k16.row.col.f32.f16.f16.f32 "
        "{%0,%1,%2,%3},{%4,%5,%6,%7},{%8,%9},{%0,%1,%2,%3};\n"
        : "+f"(d[0]), "+f"(d[1]), "+f"(d[2]), "+f"(d[3])
        : "r"(a0), "r"(a1), "r"(a2), "r"(a3), "r"(b0), "r"(b1));
}
__device__ __forceinline__ uint32_t pack_h2(float lo, float hi) {
    __half2 h = __floats2half2_rn(lo, hi);
    return *(uint32_t*)&h;
}
__device__ __forceinline__ void ldmatrix_x4_t(uint32_t r[4], uint32_t saddr) {
    asm volatile("ldmatrix.sync.aligned.m8n8.x4.trans.shared.b16 {%0,%1,%2,%3}, [%4];"
                 : "=r"(r[0]), "=r"(r[1]), "=r"(r[2]), "=r"(r[3]) : "r"(saddr));
}
__device__ __forceinline__ void ldmatrix_x4(uint32_t r[4], uint32_t saddr) {
    asm volatile("ldmatrix.sync.aligned.m8n8.x4.shared.b16 {%0,%1,%2,%3}, [%4];"
                 : "=r"(r[0]), "=r"(r[1]), "=r"(r[2]), "=r"(r[3]) : "r"(saddr));
}
__device__ __forceinline__ void cp16(uint32_t smem_dst, const void* gsrc) {
    asm volatile("cp.async.cg.shared.global [%0], [%1], 16;\n"
                 :: "r"(smem_dst), "l"(gsrc));
}
__device__ __forceinline__ float ex2f(float x) {
    float r;
    asm("ex2.approx.f32 %0, %1;" : "=f"(r) : "f"(x));
    return r;
}

#define SCQ (1.4426950408889634f / 64.f)

// ============================================================================
// W -> fp16, transposed to [n][k].  grid (64,3)
// ============================================================================
__global__ __launch_bounds__(256) void wtrans_kernel(
    const float* __restrict__ Wq, const float* __restrict__ Wk,
    const float* __restrict__ Wv)
{
    __shared__ float Ts[16][65];
    const float* src = (blockIdx.y == 0) ? Wq : (blockIdx.y == 1) ? Wk : Wv;
    const int k0 = blockIdx.x * 16;
    const int tid = threadIdx.x;
#pragma unroll
    for (int s = 0; s < 4; s++) {
        int e = tid + 256 * s;
        int kk = e >> 6, n = e & 63;
        Ts[kk][n] = src[(size_t)(k0 + kk) * HD + n];
    }
    __syncthreads();
#pragma unroll
    for (int s = 0; s < 4; s++) {
        int e = tid + 256 * s;
        int n = e >> 4, kk = e & 15;
        g_wt[blockIdx.y][(size_t)n * EMB + k0 + kk] = __float2half(Ts[kk][n]);
    }
}

// ============================================================================
// Fused projection: fragments via ldmatrix.x4 (A: 8 LDSM, B: 12 LDSM per iter
// instead of 80 LDS.32). Staging unchanged from R12.
// ============================================================================
#define PSTR 36
#define PROJ_SMEM ((2*64*PSTR + 3*2*64*PSTR) * 4)

__global__ __launch_bounds__(256, 2) void proj_kernel(const float* __restrict__ x)
{
    extern __shared__ uint32_t psm[];
    uint32_t* As = psm;
    uint32_t* Bs = psm + 2 * 64 * PSTR;
    const uint32_t As_u = (uint32_t)__cvta_generic_to_shared(As);
    const uint32_t Bs_u = (uint32_t)__cvta_generic_to_shared(Bs);

    const int m0   = blockIdx.x * 64;
    const int tid  = threadIdx.x;
    const int w    = tid >> 5;
    const int lane = tid & 31;
    const int g    = lane >> 2;
    const int t    = lane & 3;
    const int wm   = w >> 2;
    const int wn   = w & 3;

    float acc[3][2][2][4];
#pragma unroll
    for (int o = 0; o < 3; o++)
#pragma unroll
        for (int i = 0; i < 2; i++)
#pragma unroll
            for (int j = 0; j < 2; j++)
#pragma unroll
                for (int q = 0; q < 4; q++) acc[o][i][j][q] = 0.f;

    float4 pa[2][2];
    uint4  pb[3], pb2[3];

    auto ldg_iter = [&](int k0c) {
#pragma unroll
        for (int s = 0; s < 2; s++) {
            int idx = tid + 256 * s;
            int r = idx >> 3, c = idx & 7;
            const float* src = &x[(size_t)(m0 + r) * EMB + k0c + c * 8];
            pa[s][0] = *(const float4*)src;
            pa[s][1] = *(const float4*)(src + 4);
        }
#pragma unroll
        for (int o = 0; o < 3; o++) {
            int r = tid >> 3, c = tid & 7;
            pb[o] = *(const uint4*)&g_wt[o][(size_t)r * EMB + k0c + c * 8];
            int idx2 = tid + 256;
            int r2 = idx2 >> 3, c2 = idx2 & 7;
            pb2[o] = *(const uint4*)&g_wt[o][(size_t)r2 * EMB + k0c + c2 * 8];
        }
    };

    auto sts_iter = [&](int buf) {
#pragma unroll
        for (int s = 0; s < 2; s++) {
            int idx = tid + 256 * s;
            int r = idx >> 3, c = idx & 7;
            uint4 v;
            v.x = pack_h2(pa[s][0].x, pa[s][0].y);
            v.y = pack_h2(pa[s][0].z, pa[s][0].w);
            v.z = pack_h2(pa[s][1].x, pa[s][1].y);
            v.w = pack_h2(pa[s][1].z, pa[s][1].w);
            *(uint4*)&As[buf * 64 * PSTR + r * PSTR + c * 4] = v;
        }
#pragma unroll
        for (int o = 0; o < 3; o++) {
            {
                int r = tid >> 3, c = tid & 7;
                *(uint4*)&Bs[(o * 2 + buf) * 64 * PSTR + r * PSTR + c * 4] = pb[o];
            }
            {
                int idx = tid + 256;
                int r = idx >> 3, c = idx & 7;
                *(uint4*)&Bs[(o * 2 + buf) * 64 * PSTR + r * PSTR + c * 4] = pb2[o];
            }
        }
    };

    // ldmatrix lane offsets (words*4 = bytes)
    // A (m16xk16): lanes 0-15 -> m rows 0..15 (word+0); 16-31 -> same rows word+4
    const uint32_t arow_off = ((lane & 15) * PSTR + ((lane >> 4) * 4)) * 4;
    // B (n16xk16 = 2 bn blocks): lanes 0-7 n0-7 w+0; 8-15 n0-7 w+4; 16-23 n8-15 w+0; 24-31 n8-15 w+4
    const uint32_t brow_off =
        (((lane & 7) + ((lane >> 4) << 3)) * PSTR + ((lane >> 3) & 1) * 4) * 4;

    ldg_iter(0);

    for (int it = 0; it < 16; it++) {
        const int buf = it & 1;
        sts_iter(buf);
        __syncthreads();
        if (it + 1 < 16) ldg_iter((it + 1) * 64);

        const uint32_t AbU = As_u + (buf * 64 * PSTR) * 4;
#pragma unroll
        for (int ks = 0; ks < 4; ks++) {
            uint32_t a[2][4];
#pragma unroll
            for (int am = 0; am < 2; am++) {
                int rb = wm * 32 + am * 16;
                ldmatrix_x4(a[am], AbU + (rb * PSTR + ks * 8) * 4 + arow_off);
            }
#pragma unroll
            for (int o = 0; o < 3; o++) {
                const uint32_t BbU = Bs_u + ((o * 2 + buf) * 64 * PSTR) * 4;
                uint32_t bfr[4];
                ldmatrix_x4(bfr, BbU + (wn * 16 * PSTR + ks * 8) * 4 + brow_off);
#pragma unroll
                for (int am = 0; am < 2; am++) {
                    mma_f16(acc[o][am][0], a[am][0], a[am][1], a[am][2], a[am][3], bfr[0], bfr[1]);
                    mma_f16(acc[o][am][1], a[am][0], a[am][1], a[am][2], a[am][3], bfr[2], bfr[3]);
                }
            }
        }
        __syncthreads();
    }

    __half* outs[3] = {g_q, g_k, g_v};
#pragma unroll
    for (int o = 0; o < 3; o++) {
        const float sc = (o == 0) ? SCQ : 1.f;
#pragma unroll
        for (int am = 0; am < 2; am++)
#pragma unroll
            for (int bn = 0; bn < 2; bn++) {
                int r0 = m0 + wm * 32 + am * 16 + g;
                int c  = wn * 16 + bn * 8 + 2 * t;
                *(__half2*)&outs[o][(size_t)r0 * HD + c] =
                    __floats2half2_rn(acc[o][am][bn][0] * sc, acc[o][am][bn][1] * sc);
                *(__half2*)&outs[o][(size_t)(r0 + 8) * HD + c] =
                    __floats2half2_rn(acc[o][am][bn][2] * sc, acc[o][am][bn][3] * sc);
            }
    }
}

// ============================================================================
// Flash attention (R15 balanced partition) + ns==1 direct normalized write.
// ============================================================================
#define QSTR 36
#define KVW  (64*QSTR)
#define ONES_H2 0x3C003C00u

__global__ __launch_bounds__(128, 4) void attn_kernel(float* __restrict__ out)
{
    __shared__ uint32_t Qs[64 * QSTR];
    __shared__ uint32_t Ks[2][KVW];
    __shared__ uint32_t Vs[2][KVW];

    const int bx = blockIdx.x;
    const int b  = bx & 7;
    const int pair = bx >> 3;          // 0..73
    int qt, j;
    if (pair < 9)       { qt = pair;                 j = 0; }
    else if (pair < 27) { qt = 9  + (pair - 9) / 2;  j = (pair - 9) % 2; }
    else if (pair < 54) { qt = 18 + (pair - 27) / 3; j = (pair - 27) % 3; }
    else                { qt = 27 + (pair - 54) / 4; j = (pair - 54) % 4; }
    const int ns = (qt + 9) / 9;
    const int q0 = qt * 64;

    const int nk     = qt + 1;
    const int kt_beg = j * nk / ns;
    const int kt_end = (j + 1) * nk / ns;
    const int niter  = kt_end - kt_beg;

    const __half* Qg = g_q + (size_t)b * SEQ * HD;
    const __half* Kg = g_k + (size_t)b * SEQ * HD;
    const __half* Vg = g_v + (size_t)b * SEQ * HD;

    const int tid  = threadIdx.x;
    const int lane = tid & 31;
    const int w    = tid >> 5;
    const int g    = lane >> 2;
    const int t    = lane & 3;
    const int qb   = w * 16;

    const uint32_t Ks_u = (uint32_t)__cvta_generic_to_shared(Ks);
    const uint32_t Vs_u = (uint32_t)__cvta_generic_to_shared(Vs);

    auto stageKV = [&](int buf, int kt) {
        const int k0 = kt * 64;
#pragma unroll
        for (int s = 0; s < 4; s++) {
            int idx = tid + 128 * s;
            int r = idx >> 3, c = idx & 7;
            cp16(Ks_u + (buf * KVW + r * QSTR + c * 4) * 4,
                 &Kg[(size_t)(k0 + r) * HD + c * 8]);
            cp16(Vs_u + (buf * KVW + r * QSTR + c * 4) * 4,
                 &Vg[(size_t)(k0 + r) * HD + c * 8]);
        }
        asm volatile("cp.async.commit_group;\n");
    };

    if (niter > 0) stageKV(0, kt_beg);

#pragma unroll
    for (int s = 0; s < 4; s++) {
        int idx = tid + 128 * s;
        int r = idx >> 3, c = idx & 7;
        *(uint4*)&Qs[r * QSTR + c * 4] = *(const uint4*)&Qg[(size_t)(q0 + r) * HD + c * 8];
    }
    __syncthreads();

    uint32_t aQ[4][4];
#pragma unroll
    for (int ks = 0; ks < 4; ks++) {
        aQ[ks][0] = Qs[(qb + g) * QSTR + ks * 8 + t];
        aQ[ks][1] = Qs[(qb + g + 8) * QSTR + ks * 8 + t];
        aQ[ks][2] = Qs[(qb + g) * QSTR + ks * 8 + t + 4];
        aQ[ks][3] = Qs[(qb + g + 8) * QSTR + ks * 8 + t + 4];
    }

    float o_[8][4];
    float lsum[4] = {0.f, 0.f, 0.f, 0.f};
#pragma unroll
    for (int bn = 0; bn < 8; bn++)
#pragma unroll
        for (int q = 0; q < 4; q++) o_[bn][q] = 0.f;

    const uint32_t vrow_off = ((lane & 15) * QSTR + (lane >> 4) * 4) * 4;
    const uint32_t krow_off =
        (((lane & 7) + ((lane >> 4) << 3)) * QSTR + ((lane >> 3) & 1) * 4) * 4;

    for (int i = 0; i < niter; i++) {
        const int buf = i & 1;
        const int kt  = kt_beg + i;
        const int k0  = kt * 64;

        asm volatile("cp.async.wait_group 0;\n");
        __syncthreads();
        if (i + 1 < niter) stageKV(buf ^ 1, kt + 1);

        const uint32_t KbU = Ks_u + buf * KVW * 4;

        float sa[8][4];
#pragma unroll
        for (int bn = 0; bn < 8; bn++)
#pragma unroll
            for (int q = 0; q < 4; q++) sa[bn][q] = 0.f;
#pragma unroll
        for (int ks = 0; ks < 4; ks++) {
#pragma unroll
            for (int bnq = 0; bnq < 4; bnq++) {
                uint32_t kb[4];
                ldmatrix_x4(kb, KbU + (bnq * 16 * QSTR + ks * 8) * 4 + krow_off);
                mma_f16(sa[2 * bnq],     aQ[ks][0], aQ[ks][1], aQ[ks][2], aQ[ks][3], kb[0], kb[1]);
                mma_f16(sa[2 * bnq + 1], aQ[ks][0], aQ[ks][1], aQ[ks][2], aQ[ks][3], kb[2], kb[3]);
            }
        }

        if (kt == qt) {
#pragma unroll
            for (int bn = 0; bn < 8; bn++)
#pragma unroll
                for (int q = 0; q < 4; q++) {
                    int col = k0 + bn * 8 + 2 * t + (q & 1);
                    int row = q0 + qb + g + ((q >= 2) ? 8 : 0);
                    if (col > row) sa[bn][q] = -30000.f;
                }
        }

        uint32_t pA[4][4];
#pragma unroll
        for (int bn = 0; bn < 8; bn++) {
            float p0 = ex2f(sa[bn][0]);
            float p1 = ex2f(sa[bn][1]);
            float p2 = ex2f(sa[bn][2]);
            float p3 = ex2f(sa[bn][3]);
            int ks = bn >> 1;
            if ((bn & 1) == 0) {
                pA[ks][0] = pack_h2(p0, p1);
                pA[ks][1] = pack_h2(p2, p3);
            } else {
                pA[ks][2] = pack_h2(p0, p1);
                pA[ks][3] = pack_h2(p2, p3);
            }
        }

#pragma unroll
        for (int ks = 0; ks < 4; ks++)
            mma_f16(lsum, pA[ks][0], pA[ks][1], pA[ks][2], pA[ks][3], ONES_H2, ONES_H2);

        const uint32_t Vb_u = Vs_u + buf * KVW * 4;
#pragma unroll
        for (int ks = 0; ks < 4; ks++) {
#pragma unroll
            for (int bnp = 0; bnp < 4; bnp++) {
                uint32_t vb[4];
                ldmatrix_x4_t(vb, Vb_u + (ks * 16 * QSTR + bnp * 8) * 4 + vrow_off);
                mma_f16(o_[2 * bnp],     pA[ks][0], pA[ks][1], pA[ks][2], pA[ks][3], vb[0], vb[1]);
                mma_f16(o_[2 * bnp + 1], pA[ks][0], pA[ks][1], pA[ks][2], pA[ks][3], vb[2], vb[3]);
            }
        }
    }

    const int r0g = b * SEQ + q0 + qb + g;
    if (ns == 1) {
        // full row computed here: normalize and write final output directly
        float inv0 = 1.f / lsum[0];
        float inv1 = 1.f / lsum[2];
#pragma unroll
        for (int bn = 0; bn < 8; bn++) {
            int c = bn * 8 + 2 * t;
            *(float2*)&out[(size_t)r0g * HD + c] =
                make_float2(o_[bn][0] * inv0, o_[bn][1] * inv0);
            *(float2*)&out[(size_t)(r0g + 8) * HD + c] =
                make_float2(o_[bn][2] * inv1, o_[bn][3] * inv1);
        }
    } else {
        if (t == 0) {
            g_pl[j][r0g]     = lsum[0];
            g_pl[j][r0g + 8] = lsum[2];
        }
#pragma unroll
        for (int bn = 0; bn < 8; bn++) {
            int c = bn * 8 + 2 * t;
            *(float2*)&g_po[j][(size_t)r0g * HD + c] = make_float2(o_[bn][0], o_[bn][1]);
            *(float2*)&g_po[j][(size_t)(r0g + 8) * HD + c] = make_float2(o_[bn][2], o_[bn][3]);
        }
    }
}

// ============================================================================
// Merge: only rows with qt >= 9 (ns >= 2). 1472 rows per batch.
// ============================================================================
#define MROWS 1472   // SEQ - 9*64

__global__ __launch_bounds__(256) void merge_kernel(float* __restrict__ out)
{
    int gid = blockIdx.x * 256 + threadIdx.x;   // BATCH * MROWS * 16
    int row_in = gid >> 4;
    int c   = (gid & 15) * 4;
    int b   = row_in / MROWS;
    int r   = row_in - b * MROWS;
    int row = b * SEQ + 576 + r;                // 576 = 9*64
    const int qt = (576 + r) >> 6;
    const int ns = (qt + 9) / 9;

    float lacc = g_pl[0][row];
    float4 a = *(const float4*)&g_po[0][(size_t)row * HD + c];
    for (int s = 1; s < ns; s++) {
        lacc += g_pl[s][row];
        float4 bb = *(const float4*)&g_po[s][(size_t)row * HD + c];
        a.x += bb.x; a.y += bb.y; a.z += bb.z; a.w += bb.w;
    }
    float inv = 1.f / lacc;
    a.x *= inv; a.y *= inv; a.z *= inv; a.w *= inv;
    *(float4*)&out[(size_t)row * HD + c] = a;
}

// ============================================================================
extern "C" void kernel_launch(void* const* d_in, const int* in_sizes, int n_in,
                              void* d_out, int out_size)
{
    const float* x  = (const float*)d_in[0];
    const float* Wq = (const float*)d_in[1];
    const float* Wk = (const float*)d_in[2];
    const float* Wv = (const float*)d_in[3];
    float* out = (float*)d_out;

    wtrans_kernel<<<dim3(64, 3), 256>>>(Wq, Wk, Wv);

    cudaFuncSetAttribute(proj_kernel, cudaFuncAttributeMaxDynamicSharedMemorySize,
                         PROJ_SMEM);
    proj_kernel<<<NROWS / 64, 256, PROJ_SMEM>>>(x);

    attn_kernel<<<592, 128>>>(out);

    merge_kernel<<<BATCH * MROWS * 16 / 256, 256>>>(out);
}

// round 17
// speedup vs baseline: 1.4018x; 1.0274x over previous
#include <cuda_runtime.h>
#include <cuda_fp16.h>
#include <math.h>
#include <stdint.h>

#define BATCH 8
#define SEQ   2048
#define EMB   1024
#define HD    64
#define NROWS (BATCH*SEQ)   // 16384

__device__ __half g_q[NROWS*HD];     // pre-scaled by log2(e)/64
__device__ __half g_k[NROWS*HD];
__device__ __half g_v[NROWS*HD];
__device__ __half g_wt[3][EMB*HD];   // [o][k][n] natural layout, fp16
// flash-decoding partials (fixed m=0), up to 4 kv-chunks per q-tile
__device__ float g_po[4][NROWS*HD];
__device__ float g_pl[4][NROWS];

// ---------------------------------------------------------------------------
__device__ __forceinline__ void mma_f16(float d[4],
                                        uint32_t a0, uint32_t a1, uint32_t a2, uint32_t a3,
                                        uint32_t b0, uint32_t b1) {
    asm volatile(
        "mma.sync.aligned.m16n8k16.row.col.f32.f16.f16.f32 "
        "{%0,%1,%2,%3},{%4,%5,%6,%7},{%8,%9},{%0,%1,%2,%3};\n"
        : "+f"(d[0]), "+f"(d[1]), "+f"(d[2]), "+f"(d[3])
        : "r"(a0), "r"(a1), "r"(a2), "r"(a3), "r"(b0), "r"(b1));
}
__device__ __forceinline__ uint32_t pack_h2(float lo, float hi) {
    __half2 h = __floats2half2_rn(lo, hi);
    return *(uint32_t*)&h;
}
__device__ __forceinline__ void ldmatrix_x4_t(uint32_t r[4], uint32_t saddr) {
    asm volatile("ldmatrix.sync.aligned.m8n8.x4.trans.shared.b16 {%0,%1,%2,%3}, [%4];"
                 : "=r"(r[0]), "=r"(r[1]), "=r"(r[2]), "=r"(r[3]) : "r"(saddr));
}
__device__ __forceinline__ void ldmatrix_x4(uint32_t r[4], uint32_t saddr) {
    asm volatile("ldmatrix.sync.aligned.m8n8.x4.shared.b16 {%0,%1,%2,%3}, [%4];"
                 : "=r"(r[0]), "=r"(r[1]), "=r"(r[2]), "=r"(r[3]) : "r"(saddr));
}
__device__ __forceinline__ void cp16(uint32_t smem_dst, const void* gsrc) {
    asm volatile("cp.async.cg.shared.global [%0], [%1], 16;\n"
                 :: "r"(smem_dst), "l"(gsrc));
}
__device__ __forceinline__ float ex2f(float x) {
    float r;
    asm("ex2.approx.f32 %0, %1;" : "=f"(r) : "f"(x));
    return r;
}

#define SCQ (1.4426950408889634f / 64.f)

// ============================================================================
// W -> fp16, natural layout (pure cvt, fully coalesced). 3*65536 halves.
// grid 96 x 256; 8 halves per thread.
// ============================================================================
__global__ __launch_bounds__(256) void wcvt_kernel(
    const float* __restrict__ Wq, const float* __restrict__ Wk,
    const float* __restrict__ Wv)
{
    const float* src[3] = {Wq, Wk, Wv};
    int gid = blockIdx.x * 256 + threadIdx.x;   // 24576 threads
    int o   = gid >> 13;                        // / 8192
    int e8  = gid & 8191;
    const float* s = src[o] + e8 * 8;
    float4 v0 = *(const float4*)s;
    float4 v1 = *(const float4*)(s + 4);
    uint4 u;
    u.x = pack_h2(v0.x, v0.y);
    u.y = pack_h2(v0.z, v0.w);
    u.z = pack_h2(v1.x, v1.y);
    u.w = pack_h2(v1.z, v1.w);
    *(uint4*)&g_wt[o][e8 * 8] = u;
}

// ============================================================================
// Fused projection: A frags via ldmatrix.x4, B frags via ldmatrix.x4.trans
// from natural [k][n] tiles (V-pattern from attn). Staging unchanged.
// ============================================================================
#define PSTR 36
#define PROJ_SMEM ((2*64*PSTR + 3*2*64*PSTR) * 4)

__global__ __launch_bounds__(256, 2) void proj_kernel(const float* __restrict__ x)
{
    extern __shared__ uint32_t psm[];
    uint32_t* As = psm;
    uint32_t* Bs = psm + 2 * 64 * PSTR;
    const uint32_t As_u = (uint32_t)__cvta_generic_to_shared(As);
    const uint32_t Bs_u = (uint32_t)__cvta_generic_to_shared(Bs);

    const int m0   = blockIdx.x * 64;
    const int tid  = threadIdx.x;
    const int w    = tid >> 5;
    const int lane = tid & 31;
    const int g    = lane >> 2;
    const int t    = lane & 3;
    const int wm   = w >> 2;
    const int wn   = w & 3;

    float acc[3][2][2][4];
#pragma unroll
    for (int o = 0; o < 3; o++)
#pragma unroll
        for (int i = 0; i < 2; i++)
#pragma unroll
            for (int j = 0; j < 2; j++)
#pragma unroll
                for (int q = 0; q < 4; q++) acc[o][i][j][q] = 0.f;

    float4 pa[2][2];
    uint4  pb[3], pb2[3];

    auto ldg_iter = [&](int k0c) {
#pragma unroll
        for (int s = 0; s < 2; s++) {
            int idx = tid + 256 * s;
            int r = idx >> 3, c = idx & 7;
            const float* src = &x[(size_t)(m0 + r) * EMB + k0c + c * 8];
            pa[s][0] = *(const float4*)src;
            pa[s][1] = *(const float4*)(src + 4);
        }
        // B tile [k][n]: 64 k-rows x 64 n halves = 512 uint4, 2/thread
#pragma unroll
        for (int o = 0; o < 3; o++) {
            int r = tid >> 3, c = tid & 7;
            pb[o] = *(const uint4*)&g_wt[o][(size_t)(k0c + r) * HD + c * 8];
            int idx2 = tid + 256;
            int r2 = idx2 >> 3, c2 = idx2 & 7;
            pb2[o] = *(const uint4*)&g_wt[o][(size_t)(k0c + r2) * HD + c2 * 8];
        }
    };

    auto sts_iter = [&](int buf) {
#pragma unroll
        for (int s = 0; s < 2; s++) {
            int idx = tid + 256 * s;
            int r = idx >> 3, c = idx & 7;
            uint4 v;
            v.x = pack_h2(pa[s][0].x, pa[s][0].y);
            v.y = pack_h2(pa[s][0].z, pa[s][0].w);
            v.z = pack_h2(pa[s][1].x, pa[s][1].y);
            v.w = pack_h2(pa[s][1].z, pa[s][1].w);
            *(uint4*)&As[buf * 64 * PSTR + r * PSTR + c * 4] = v;
        }
#pragma unroll
        for (int o = 0; o < 3; o++) {
            {
                int r = tid >> 3, c = tid & 7;
                *(uint4*)&Bs[(o * 2 + buf) * 64 * PSTR + r * PSTR + c * 4] = pb[o];
            }
            {
                int idx = tid + 256;
                int r = idx >> 3, c = idx & 7;
                *(uint4*)&Bs[(o * 2 + buf) * 64 * PSTR + r * PSTR + c * 4] = pb2[o];
            }
        }
    };

    // A (m16xk16) non-trans lane offset
    const uint32_t arow_off = ((lane & 15) * PSTR + ((lane >> 4) * 4)) * 4;
    // B trans lane offset (identical to attn's V pattern, stride 36)
    const uint32_t trow_off = ((lane & 15) * PSTR + ((lane >> 4) * 4)) * 4;

    ldg_iter(0);

    for (int it = 0; it < 16; it++) {
        const int buf = it & 1;
        sts_iter(buf);
        __syncthreads();
        if (it + 1 < 16) ldg_iter((it + 1) * 64);

        const uint32_t AbU = As_u + (buf * 64 * PSTR) * 4;
#pragma unroll
        for (int ks = 0; ks < 4; ks++) {
            uint32_t a[2][4];
#pragma unroll
            for (int am = 0; am < 2; am++) {
                int rb = wm * 32 + am * 16;
                ldmatrix_x4(a[am], AbU + (rb * PSTR + ks * 8) * 4 + arow_off);
            }
#pragma unroll
            for (int o = 0; o < 3; o++) {
                const uint32_t BbU = Bs_u + ((o * 2 + buf) * 64 * PSTR) * 4;
                uint32_t bfr[4];
                // rows ks*16 (k16 chunk), n cols wn*16..+16 (wn*8 words)
                ldmatrix_x4_t(bfr, BbU + (ks * 16 * PSTR + wn * 8) * 4 + trow_off);
#pragma unroll
                for (int am = 0; am < 2; am++) {
                    mma_f16(acc[o][am][0], a[am][0], a[am][1], a[am][2], a[am][3], bfr[0], bfr[1]);
                    mma_f16(acc[o][am][1], a[am][0], a[am][1], a[am][2], a[am][3], bfr[2], bfr[3]);
                }
            }
        }
        __syncthreads();
    }

    __half* outs[3] = {g_q, g_k, g_v};
#pragma unroll
    for (int o = 0; o < 3; o++) {
        const float sc = (o == 0) ? SCQ : 1.f;
#pragma unroll
        for (int am = 0; am < 2; am++)
#pragma unroll
            for (int bn = 0; bn < 2; bn++) {
                int r0 = m0 + wm * 32 + am * 16 + g;
                int c  = wn * 16 + bn * 8 + 2 * t;
                *(__half2*)&outs[o][(size_t)r0 * HD + c] =
                    __floats2half2_rn(acc[o][am][bn][0] * sc, acc[o][am][bn][1] * sc);
                *(__half2*)&outs[o][(size_t)(r0 + 8) * HD + c] =
                    __floats2half2_rn(acc[o][am][bn][2] * sc, acc[o][am][bn][3] * sc);
            }
    }
}

// ============================================================================
// Flash attention (R16: balanced partition + direct write) — unchanged.
// ============================================================================
#define QSTR 36
#define KVW  (64*QSTR)
#define ONES_H2 0x3C003C00u

__global__ __launch_bounds__(128, 4) void attn_kernel(float* __restrict__ out)
{
    __shared__ uint32_t Qs[64 * QSTR];
    __shared__ uint32_t Ks[2][KVW];
    __shared__ uint32_t Vs[2][KVW];

    const int bx = blockIdx.x;
    const int b  = bx & 7;
    const int pair = bx >> 3;
    int qt, j;
    if (pair < 9)       { qt = pair;                 j = 0; }
    else if (pair < 27) { qt = 9  + (pair - 9) / 2;  j = (pair - 9) % 2; }
    else if (pair < 54) { qt = 18 + (pair - 27) / 3; j = (pair - 27) % 3; }
    else                { qt = 27 + (pair - 54) / 4; j = (pair - 54) % 4; }
    const int ns = (qt + 9) / 9;
    const int q0 = qt * 64;

    const int nk     = qt + 1;
    const int kt_beg = j * nk / ns;
    const int kt_end = (j + 1) * nk / ns;
    const int niter  = kt_end - kt_beg;

    const __half* Qg = g_q + (size_t)b * SEQ * HD;
    const __half* Kg = g_k + (size_t)b * SEQ * HD;
    const __half* Vg = g_v + (size_t)b * SEQ * HD;

    const int tid  = threadIdx.x;
    const int lane = tid & 31;
    const int w    = tid >> 5;
    const int g    = lane >> 2;
    const int t    = lane & 3;
    const int qb   = w * 16;

    const uint32_t Ks_u = (uint32_t)__cvta_generic_to_shared(Ks);
    const uint32_t Vs_u = (uint32_t)__cvta_generic_to_shared(Vs);

    auto stageKV = [&](int buf, int kt) {
        const int k0 = kt * 64;
#pragma unroll
        for (int s = 0; s < 4; s++) {
            int idx = tid + 128 * s;
            int r = idx >> 3, c = idx & 7;
            cp16(Ks_u + (buf * KVW + r * QSTR + c * 4) * 4,
                 &Kg[(size_t)(k0 + r) * HD + c * 8]);
            cp16(Vs_u + (buf * KVW + r * QSTR + c * 4) * 4,
                 &Vg[(size_t)(k0 + r) * HD + c * 8]);
        }
        asm volatile("cp.async.commit_group;\n");
    };

    if (niter > 0) stageKV(0, kt_beg);

#pragma unroll
    for (int s = 0; s < 4; s++) {
        int idx = tid + 128 * s;
        int r = idx >> 3, c = idx & 7;
        *(uint4*)&Qs[r * QSTR + c * 4] = *(const uint4*)&Qg[(size_t)(q0 + r) * HD + c * 8];
    }
    __syncthreads();

    uint32_t aQ[4][4];
#pragma unroll
    for (int ks = 0; ks < 4; ks++) {
        aQ[ks][0] = Qs[(qb + g) * QSTR + ks * 8 + t];
        aQ[ks][1] = Qs[(qb + g + 8) * QSTR + ks * 8 + t];
        aQ[ks][2] = Qs[(qb + g) * QSTR + ks * 8 + t + 4];
        aQ[ks][3] = Qs[(qb + g + 8) * QSTR + ks * 8 + t + 4];
    }

    float o_[8][4];
    float lsum[4] = {0.f, 0.f, 0.f, 0.f};
#pragma unroll
    for (int bn = 0; bn < 8; bn++)
#pragma unroll
        for (int q = 0; q < 4; q++) o_[bn][q] = 0.f;

    const uint32_t vrow_off = ((lane & 15) * QSTR + (lane >> 4) * 4) * 4;
    const uint32_t krow_off =
        (((lane & 7) + ((lane >> 4) << 3)) * QSTR + ((lane >> 3) & 1) * 4) * 4;

    for (int i = 0; i < niter; i++) {
        const int buf = i & 1;
        const int kt  = kt_beg + i;
        const int k0  = kt * 64;

        asm volatile("cp.async.wait_group 0;\n");
        __syncthreads();
        if (i + 1 < niter) stageKV(buf ^ 1, kt + 1);

        const uint32_t KbU = Ks_u + buf * KVW * 4;

        float sa[8][4];
#pragma unroll
        for (int bn = 0; bn < 8; bn++)
#pragma unroll
            for (int q = 0; q < 4; q++) sa[bn][q] = 0.f;
#pragma unroll
        for (int ks = 0; ks < 4; ks++) {
#pragma unroll
            for (int bnq = 0; bnq < 4; bnq++) {
                uint32_t kb[4];
                ldmatrix_x4(kb, KbU + (bnq * 16 * QSTR + ks * 8) * 4 + krow_off);
                mma_f16(sa[2 * bnq],     aQ[ks][0], aQ[ks][1], aQ[ks][2], aQ[ks][3], kb[0], kb[1]);
                mma_f16(sa[2 * bnq + 1], aQ[ks][0], aQ[ks][1], aQ[ks][2], aQ[ks][3], kb[2], kb[3]);
            }
        }

        if (kt == qt) {
#pragma unroll
            for (int bn = 0; bn < 8; bn++)
#pragma unroll
                for (int q = 0; q < 4; q++) {
                    int col = k0 + bn * 8 + 2 * t + (q & 1);
                    int row = q0 + qb + g + ((q >= 2) ? 8 : 0);
                    if (col > row) sa[bn][q] = -30000.f;
                }
        }

        uint32_t pA[4][4];
#pragma unroll
        for (int bn = 0; bn < 8; bn++) {
            float p0 = ex2f(sa[bn][0]);
            float p1 = ex2f(sa[bn][1]);
            float p2 = ex2f(sa[bn][2]);
            float p3 = ex2f(sa[bn][3]);
            int ks = bn >> 1;
            if ((bn & 1) == 0) {
                pA[ks][0] = pack_h2(p0, p1);
                pA[ks][1] = pack_h2(p2, p3);
            } else {
                pA[ks][2] = pack_h2(p0, p1);
                pA[ks][3] = pack_h2(p2, p3);
            }
        }

#pragma unroll
        for (int ks = 0; ks < 4; ks++)
            mma_f16(lsum, pA[ks][0], pA[ks][1], pA[ks][2], pA[ks][3], ONES_H2, ONES_H2);

        const uint32_t Vb_u = Vs_u + buf * KVW * 4;
#pragma unroll
        for (int ks = 0; ks < 4; ks++) {
#pragma unroll
            for (int bnp = 0; bnp < 4; bnp++) {
                uint32_t vb[4];
                ldmatrix_x4_t(vb, Vb_u + (ks * 16 * QSTR + bnp * 8) * 4 + vrow_off);
                mma_f16(o_[2 * bnp],     pA[ks][0], pA[ks][1], pA[ks][2], pA[ks][3], vb[0], vb[1]);
                mma_f16(o_[2 * bnp + 1], pA[ks][0], pA[ks][1], pA[ks][2], pA[ks][3], vb[2], vb[3]);
            }
        }
    }

    const int r0g = b * SEQ + q0 + qb + g;
    if (ns == 1) {
        float inv0 = 1.f / lsum[0];
        float inv1 = 1.f / lsum[2];
#pragma unroll
        for (int bn = 0; bn < 8; bn++) {
            int c = bn * 8 + 2 * t;
            *(float2*)&out[(size_t)r0g * HD + c] =
                make_float2(o_[bn][0] * inv0, o_[bn][1] * inv0);
            *(float2*)&out[(size_t)(r0g + 8) * HD + c] =
                make_float2(o_[bn][2] * inv1, o_[bn][3] * inv1);
        }
    } else {
        if (t == 0) {
            g_pl[j][r0g]     = lsum[0];
            g_pl[j][r0g + 8] = lsum[2];
        }
#pragma unroll
        for (int bn = 0; bn < 8; bn++) {
            int c = bn * 8 + 2 * t;
            *(float2*)&g_po[j][(size_t)r0g * HD + c] = make_float2(o_[bn][0], o_[bn][1]);
            *(float2*)&g_po[j][(size_t)(r0g + 8) * HD + c] = make_float2(o_[bn][2], o_[bn][3]);
        }
    }
}

// ============================================================================
// Merge: rows with qt >= 9; 8 threads/row x 8 floats -> high MLP.
// ============================================================================
#define MROWS 1472   // SEQ - 9*64

__global__ __launch_bounds__(256) void merge_kernel(float* __restrict__ out)
{
    int gid = blockIdx.x * 256 + threadIdx.x;   // BATCH * MROWS * 8
    int row_in = gid >> 3;
    int c   = (gid & 7) * 8;
    int b   = row_in / MROWS;
    int r   = row_in - b * MROWS;
    int row = b * SEQ + 576 + r;
    const int qt = (576 + r) >> 6;
    const int ns = (qt + 9) / 9;

    // issue all loads up-front (up to 8 f4 + 4 scalars in flight)
    float4 a0[4], a1[4];
    float  lv[4];
#pragma unroll
    for (int s = 0; s < 4; s++) {
        if (s < ns) {
            const float* p = &g_po[s][(size_t)row * HD + c];
            a0[s] = *(const float4*)p;
            a1[s] = *(const float4*)(p + 4);
            lv[s] = g_pl[s][row];
        }
    }
    float lacc = lv[0];
    float4 r0 = a0[0], r1 = a1[0];
#pragma unroll
    for (int s = 1; s < 4; s++) {
        if (s < ns) {
            lacc += lv[s];
            r0.x += a0[s].x; r0.y += a0[s].y; r0.z += a0[s].z; r0.w += a0[s].w;
            r1.x += a1[s].x; r1.y += a1[s].y; r1.z += a1[s].z; r1.w += a1[s].w;
        }
    }
    float inv = 1.f / lacc;
    r0.x *= inv; r0.y *= inv; r0.z *= inv; r0.w *= inv;
    r1.x *= inv; r1.y *= inv; r1.z *= inv; r1.w *= inv;
    float* dst = &out[(size_t)row * HD + c];
    *(float4*)dst = r0;
    *(float4*)(dst + 4) = r1;
}

// ============================================================================
extern "C" void kernel_launch(void* const* d_in, const int* in_sizes, int n_in,
                              void* d_out, int out_size)
{
    const float* x  = (const float*)d_in[0];
    const float* Wq = (const float*)d_in[1];
    const float* Wk = (const float*)d_in[2];
    const float* Wv = (const float*)d_in[3];
    float* out = (float*)d_out;

    wcvt_kernel<<<96, 256>>>(Wq, Wk, Wv);

    cudaFuncSetAttribute(proj_kernel, cudaFuncAttributeMaxDynamicSharedMemorySize,
                         PROJ_SMEM);
    proj_kernel<<<NROWS / 64, 256, PROJ_SMEM>>>(x);

    attn_kernel<<<592, 128>>>(out);

    merge_kernel<<<BATCH * MROWS * 8 / 256, 256>>>(out);
}